// round 8
// baseline (speedup 1.0000x reference)
#include <cuda_runtime.h>
#include <cuda_bf16.h>
#include <math.h>

// ---------------- problem constants ----------------
#define HIMG 256
#define WIMG 256
#define NPIX 65536            // HIMG*WIMG
#define CDIM 180
#define NHEADS 6
#define HD 30                 // CDIM / NHEADS
#define WS 16
#define OWS 24
#define PADW 4                // (OWS-WS)/2
#define NWIN 16               // windows per side
#define NQ 256                // WS*WS
#define NKEY 576              // OWS*OWS
#define MLPH 360
#define QKVN 540              // 180 (q) + 360 (kv)

// ---------------- scratch (device globals; no allocation allowed) ----------------
__device__ float  g_qkv [NPIX*QKVN];        // [pix][q(180) | k(180) | v(180)]
__device__ float  g_qkvw[CDIM*QKVN];        // packed [k][540] weights
__device__ float  g_qkvb[QKVN];             // packed bias
__device__ float  g_biasQ[NHEADS*NQ*NKEY];  // [head][query][key]
__device__ float2 g_ln1 [NPIX];             // {mu, inv} of x
__device__ float2 g_ln2 [NPIX];             // {mu, inv} of xo
__device__ float  g_ao [NPIX*CDIM];
__device__ float  g_xo [NPIX*CDIM];
__device__ float  g_mh [NPIX*MLPH];

// ---------------- LN stats: one warp per row of 180 -> {mu, inv} ----------------
__global__ void ln_stats_kernel(const float* __restrict__ x, float2* __restrict__ st) {
    int row  = blockIdx.x * blockDim.y + threadIdx.y;
    int lane = threadIdx.x;
    const float* xr = x + (size_t)row * CDIM;
    float v[6];
    float s = 0.f;
#pragma unroll
    for (int i = 0; i < 6; i++) {
        int d = lane + 32 * i;
        v[i] = (d < CDIM) ? xr[d] : 0.f;
        s += v[i];
    }
#pragma unroll
    for (int o = 16; o > 0; o >>= 1) s += __shfl_xor_sync(0xffffffffu, s, o);
    float mu = s * (1.f / CDIM);
    float vs = 0.f;
#pragma unroll
    for (int i = 0; i < 6; i++) {
        int d = lane + 32 * i;
        float dv = (d < CDIM) ? (v[i] - mu) : 0.f;
        vs += dv * dv;
    }
#pragma unroll
    for (int o = 16; o > 0; o >>= 1) vs += __shfl_xor_sync(0xffffffffu, vs, o);
    float inv = rsqrtf(vs * (1.f / CDIM) + 1e-5f);
    if (lane == 0) st[row] = make_float2(mu, inv);
}

// ---------------- pack [q_w | kv_w] -> g_qkvw, [q_b | kv_b] -> g_qkvb ----------------
__global__ void pack_qkv_kernel(const float* __restrict__ q_w, const float* __restrict__ kv_w,
                                const float* __restrict__ q_b, const float* __restrict__ kv_b) {
    int idx = blockIdx.x * blockDim.x + threadIdx.x;
    if (idx < CDIM * QKVN) {
        int k = idx / QKVN, n = idx - k * QKVN;
        g_qkvw[idx] = (n < CDIM) ? q_w[k * CDIM + n] : kv_w[k * 2 * CDIM + (n - CDIM)];
    }
    if (idx < QKVN)
        g_qkvb[idx] = (idx < CDIM) ? q_b[idx] : kv_b[idx - CDIM];
}

// ---------------- bias precompute: biasQ[h][q][k] = table[rpi[q,k], h] ----------------
__global__ void bias_kernel(const int* __restrict__ rpi, const float* __restrict__ table) {
    int q = blockIdx.x;       // 0..255
    int k = threadIdx.x;      // 0..575
    int t = rpi[q * NKEY + k];
#pragma unroll
    for (int h = 0; h < NHEADS; h++)
        g_biasQ[((size_t)h * NQ + q) * NKEY + k] = table[t * NHEADS + h];
}

// ---------------- tf32 tensor-core GEMM, double-buffered, paired smem ----------------
// C = act(lnA(A)@B + bias [+ res]). Optional fused LayerNorm on A rows (LNA=1):
// a[m][k] = (A[m][k]-mu[m])*inv[m]*gamma[k] + beta[k], stats precomputed.
__device__ __forceinline__ unsigned f2tf32(float v) {
    unsigned u;
    asm("cvt.rna.tf32.f32 %0, %1;" : "=r"(u) : "f"(v));
    return u;
}

#define AS_T  132
#define AS_KS 532
#define ABUF  2128      // 4*AS_KS (uint2)
#define BS_T  68
#define BS_KS 273
#define BBUF  1092      // 4*BS_KS (uint2)
#define STGSZ (ABUF + BBUF)               // 3220 uint2 per stage
#define GEMM_SMEM (2 * STGSZ * 8)         // 51520 bytes

template<int ACT, int LNA>
__global__ void __launch_bounds__(256, 2) mma_gemm(
    const float* __restrict__ A, const float* __restrict__ B,
    const float* __restrict__ bias, const float* __restrict__ res,
    float* __restrict__ C,
    const float2* __restrict__ lnst, const float* __restrict__ lng,
    const float* __restrict__ lnb,
    int M, int N, int K)
{
    extern __shared__ uint2 smbuf[];

    int bm = blockIdx.y * 128;
    int bn = blockIdx.x * 64;
    int t    = threadIdx.x;
    int lane = t & 31;
    int warp = t >> 5;
    int g  = lane >> 2;
    int tq = lane & 3;
    int wm = (warp >> 1) * 32;
    int wn = (warp & 1) * 32;

    float acc[2][4][4];
#pragma unroll
    for (int mi = 0; mi < 2; mi++)
#pragma unroll
        for (int ni = 0; ni < 4; ni++)
#pragma unroll
            for (int r = 0; r < 4; r++) acc[mi][ni][r] = 0.f;

    int kIters = (K + 31) >> 5;
    float4 ra[4], rb[2];

    auto gload = [&](int it) {
        int k0 = it * 32;
#pragma unroll
        for (int i = 0; i < 4; i++) {
            int idx = t + 256 * i;
            int m = idx >> 3, j = idx & 7;
            int gk = k0 + 4 * j;
            if (gk < K) {
                float4 v = *(const float4*)&A[(size_t)(bm + m) * K + gk];
                if (LNA) {
                    float2 st = lnst[bm + m];
                    float4 ga = *(const float4*)&lng[gk];
                    float4 be = *(const float4*)&lnb[gk];
                    v.x = (v.x - st.x) * st.y * ga.x + be.x;
                    v.y = (v.y - st.x) * st.y * ga.y + be.y;
                    v.z = (v.z - st.x) * st.y * ga.z + be.z;
                    v.w = (v.w - st.x) * st.y * ga.w + be.w;
                }
                ra[i] = v;
            } else {
                ra[i] = make_float4(0.f, 0.f, 0.f, 0.f);
            }
        }
#pragma unroll
        for (int i = 0; i < 2; i++) {
            int idx = t + 256 * i;
            int k = idx & 31, n = 4 * (idx >> 5);
            int gk = k0 + k, gn = bn + n;
            rb[i] = (gk < K && gn < N) ? *(const float4*)&B[(size_t)gk * N + gn]
                                       : make_float4(0.f, 0.f, 0.f, 0.f);
        }
    };

    auto sstore = [&](int s) {
        unsigned* ab = (unsigned*)(smbuf + s * STGSZ);
        unsigned* bb = (unsigned*)(smbuf + s * STGSZ + ABUF);
#pragma unroll
        for (int i = 0; i < 4; i++) {
            int idx = t + 256 * i;
            int m = idx >> 3, j = idx & 7;
            int ks = j >> 1, sel = j & 1;
            unsigned base = 2 * (ks * AS_KS + m) + sel;
            ab[base + 2 * (0 * AS_T)] = f2tf32(ra[i].x);
            ab[base + 2 * (1 * AS_T)] = f2tf32(ra[i].y);
            ab[base + 2 * (2 * AS_T)] = f2tf32(ra[i].z);
            ab[base + 2 * (3 * AS_T)] = f2tf32(ra[i].w);
        }
#pragma unroll
        for (int i = 0; i < 2; i++) {
            int idx = t + 256 * i;
            int k = idx & 31, n = 4 * (idx >> 5);
            int ks = k >> 3, tqq = k & 3, sel = (k >> 2) & 1;
            unsigned base = 2 * (ks * BS_KS + tqq * BS_T + n) + sel;
            bb[base + 0] = f2tf32(rb[i].x);
            bb[base + 2] = f2tf32(rb[i].y);
            bb[base + 4] = f2tf32(rb[i].z);
            bb[base + 6] = f2tf32(rb[i].w);
        }
    };

    auto compute = [&](int s) {
        const uint2* as = smbuf + s * STGSZ;
        const uint2* bs = as + ABUF;
#pragma unroll
        for (int ks = 0; ks < 4; ks++) {
            uint2 aLo[2], aHi[2], bp[4];
#pragma unroll
            for (int mi = 0; mi < 2; mi++) {
                int m0 = wm + mi * 16 + g;
                aLo[mi] = as[ks * AS_KS + tq * AS_T + m0];
                aHi[mi] = as[ks * AS_KS + tq * AS_T + m0 + 8];
            }
#pragma unroll
            for (int ni = 0; ni < 4; ni++)
                bp[ni] = bs[ks * BS_KS + tq * BS_T + wn + ni * 8 + g];
#pragma unroll
            for (int mi = 0; mi < 2; mi++)
#pragma unroll
                for (int ni = 0; ni < 4; ni++) {
                    asm volatile(
                        "mma.sync.aligned.m16n8k8.row.col.f32.tf32.tf32.f32 "
                        "{%0,%1,%2,%3}, {%4,%5,%6,%7}, {%8,%9}, {%0,%1,%2,%3};"
                        : "+f"(acc[mi][ni][0]), "+f"(acc[mi][ni][1]),
                          "+f"(acc[mi][ni][2]), "+f"(acc[mi][ni][3])
                        : "r"(aLo[mi].x), "r"(aHi[mi].x),
                          "r"(aLo[mi].y), "r"(aHi[mi].y),
                          "r"(bp[ni].x), "r"(bp[ni].y));
                }
        }
    };

    gload(0);
    sstore(0);
    __syncthreads();
    for (int it = 0; it < kIters; it++) {
        if (it + 1 < kIters) gload(it + 1);
        compute(it & 1);
        if (it + 1 < kIters) {
            sstore((it + 1) & 1);
            __syncthreads();
        }
    }

#pragma unroll
    for (int mi = 0; mi < 2; mi++) {
#pragma unroll
        for (int ni = 0; ni < 4; ni++) {
            int n = bn + wn + ni * 8 + 2 * tq;
            if (n >= N) continue;
            float bn0 = bias[n], bn1 = bias[n + 1];
#pragma unroll
            for (int half = 0; half < 2; half++) {
                int m = bm + wm + mi * 16 + g + half * 8;
                float v0 = acc[mi][ni][half * 2 + 0] + bn0;
                float v1 = acc[mi][ni][half * 2 + 1] + bn1;
                if (res) {
                    v0 += res[(size_t)m * N + n];
                    v1 += res[(size_t)m * N + n + 1];
                }
                if (ACT == 1) {
                    v0 = v0 * normcdff(v0);
                    v1 = v1 * normcdff(v1);
                }
                C[(size_t)m * N + n]     = v0;
                C[(size_t)m * N + n + 1] = v1;
            }
        }
    }
}

// ---------------- bf16 tensor-core windowed attention ----------------
// grid (256 windows, 6 heads), 256 threads = 8 warps, each warp owns 32 query
// rows. 9 chunks of 64 keys, no-max softmax (scores |s| << 1). OOB keys staged
// as zeros -> contribute exp(bias) to the denominator with v=0 (reference pad).
// Reads q/k/v from the merged g_qkv buffer (row stride 540).
__device__ __forceinline__ void mma_bf16(float* c, unsigned a0, unsigned a1,
                                         unsigned a2, unsigned a3,
                                         unsigned b0, unsigned b1) {
    asm volatile(
        "mma.sync.aligned.m16n8k16.row.col.f32.bf16.bf16.f32 "
        "{%0,%1,%2,%3}, {%4,%5,%6,%7}, {%8,%9}, {%0,%1,%2,%3};"
        : "+f"(c[0]), "+f"(c[1]), "+f"(c[2]), "+f"(c[3])
        : "r"(a0), "r"(a1), "r"(a2), "r"(a3), "r"(b0), "r"(b1));
}

__global__ void __launch_bounds__(256, 2) attn_mma_kernel() {
    int win  = blockIdx.x;
    int head = blockIdx.y;
    int wi = win >> 4, wj = win & 15;
    int t    = threadIdx.x;
    int lane = t & 31;
    int warp = t >> 5;
    int g  = lane >> 2;
    int tq = lane & 3;
    int wq = warp * 32;

    __shared__ __nv_bfloat16 Qs[NQ][40];    // stride 40: bank 20g+tq, conflict-free
    __shared__ __nv_bfloat16 Ks[64][40];
    __shared__ __nv_bfloat16 VsT[32][72];   // stride 72: rows 30/31 zeroed

    const float scale = 0.18257418583505537f;  // 30^-0.5

    // ---- stage Q (once) ----
    {
        int qi = t >> 4, qj = t & 15;
        int pix = (wi * WS + qi) * WIMG + (wj * WS + qj);
        const float* src = g_qkv + (size_t)pix * QKVN + head * HD;
#pragma unroll
        for (int j = 0; j < 15; j++) {
            float2 v = *(const float2*)&src[2 * j];
            *(__nv_bfloat162*)&Qs[t][2 * j] =
                __floats2bfloat162_rn(v.x * scale, v.y * scale);
        }
        *(__nv_bfloat162*)&Qs[t][30] = __floats2bfloat162_rn(0.f, 0.f);
    }
    __syncthreads();

    unsigned aq[2][2][4];
#pragma unroll
    for (int mi = 0; mi < 2; mi++) {
        int q0 = wq + mi * 16 + g, q1 = q0 + 8;
#pragma unroll
        for (int ks = 0; ks < 2; ks++) {
            int c0 = ks * 16 + 2 * tq;
            aq[mi][ks][0] = *(const unsigned*)&Qs[q0][c0];
            aq[mi][ks][1] = *(const unsigned*)&Qs[q1][c0];
            aq[mi][ks][2] = *(const unsigned*)&Qs[q0][c0 + 8];
            aq[mi][ks][3] = *(const unsigned*)&Qs[q1][c0 + 8];
        }
    }

    float O[2][4][4];
#pragma unroll
    for (int mi = 0; mi < 2; mi++)
#pragma unroll
        for (int nj = 0; nj < 4; nj++)
#pragma unroll
            for (int r = 0; r < 4; r++) O[mi][nj][r] = 0.f;
    float l0[2] = {0.f, 0.f}, l1[2] = {0.f, 0.f};

    int half  = t >> 7;         // 0: stage K, 1: stage V
    int key_l = (t & 127) >> 1; // key within chunk
    int part  = t & 1;          // which 15-dim half

    for (int ch = 0; ch < 9; ch++) {
        int cb = ch * 64;
        __syncthreads();
        {
            int key = cb + key_l;
            int ki = key / OWS;
            int kj = key - ki * OWS;
            int gr = wi * WS - PADW + ki;
            int gc = wj * WS - PADW + kj;
            bool ok = ((unsigned)gr < HIMG) && ((unsigned)gc < WIMG);
            const float* src = g_qkv + ((size_t)(gr * WIMG + gc)) * QKVN
                               + CDIM + half * CDIM + head * HD + part * 15;
            if (half == 0) {
#pragma unroll
                for (int d = 0; d < 15; d++)
                    Ks[key_l][part * 15 + d] = __float2bfloat16(ok ? src[d] : 0.f);
                if (part == 0)
                    *(__nv_bfloat162*)&Ks[key_l][30] = __floats2bfloat162_rn(0.f, 0.f);
            } else {
#pragma unroll
                for (int d = 0; d < 15; d++)
                    VsT[part * 15 + d][key_l] = __float2bfloat16(ok ? src[d] : 0.f);
                if (part == 0) {
                    VsT[30][key_l] = __float2bfloat16(0.f);
                    VsT[31][key_l] = __float2bfloat16(0.f);
                }
            }
        }
        __syncthreads();

        unsigned P[2][8][2];
#pragma unroll
        for (int mi = 0; mi < 2; mi++) {
            int q0 = wq + mi * 16 + g, q1 = q0 + 8;
            const float* bp0 = g_biasQ + ((size_t)head * NQ + q0) * NKEY + cb + 2 * tq;
            const float* bp1 = g_biasQ + ((size_t)head * NQ + q1) * NKEY + cb + 2 * tq;
#pragma unroll
            for (int ni = 0; ni < 8; ni++) {
                float c[4] = {0.f, 0.f, 0.f, 0.f};
                int krow = ni * 8 + g;
#pragma unroll
                for (int ks = 0; ks < 2; ks++) {
                    unsigned b0 = *(const unsigned*)&Ks[krow][ks * 16 + 2 * tq];
                    unsigned b1 = *(const unsigned*)&Ks[krow][ks * 16 + 2 * tq + 8];
                    mma_bf16(c, aq[mi][ks][0], aq[mi][ks][1], aq[mi][ks][2], aq[mi][ks][3], b0, b1);
                }
                float2 bA = *(const float2*)&bp0[ni * 8];
                float2 bB = *(const float2*)&bp1[ni * 8];
                float p0 = __expf(c[0] + bA.x);
                float p1 = __expf(c[1] + bA.y);
                float p2 = __expf(c[2] + bB.x);
                float p3 = __expf(c[3] + bB.y);
                l0[mi] += p0 + p1;
                l1[mi] += p2 + p3;
                __nv_bfloat162 h0 = __floats2bfloat162_rn(p0, p1);
                __nv_bfloat162 h1 = __floats2bfloat162_rn(p2, p3);
                P[mi][ni][0] = *(unsigned*)&h0;
                P[mi][ni][1] = *(unsigned*)&h1;
            }
        }

#pragma unroll
        for (int mi = 0; mi < 2; mi++)
#pragma unroll
            for (int nj = 0; nj < 4; nj++) {
                int drow = nj * 8 + g;
#pragma unroll
                for (int ks = 0; ks < 4; ks++) {
                    unsigned b0 = *(const unsigned*)&VsT[drow][ks * 16 + 2 * tq];
                    unsigned b1 = *(const unsigned*)&VsT[drow][ks * 16 + 2 * tq + 8];
                    mma_bf16(O[mi][nj],
                             P[mi][2 * ks][0], P[mi][2 * ks][1],
                             P[mi][2 * ks + 1][0], P[mi][2 * ks + 1][1],
                             b0, b1);
                }
            }
    }

#pragma unroll
    for (int mi = 0; mi < 2; mi++) {
        l0[mi] += __shfl_xor_sync(0xffffffffu, l0[mi], 1);
        l0[mi] += __shfl_xor_sync(0xffffffffu, l0[mi], 2);
        l1[mi] += __shfl_xor_sync(0xffffffffu, l1[mi], 1);
        l1[mi] += __shfl_xor_sync(0xffffffffu, l1[mi], 2);
    }
#pragma unroll
    for (int mi = 0; mi < 2; mi++) {
        float inv0 = 1.f / l0[mi];
        float inv1 = 1.f / l1[mi];
        int q0 = wq + mi * 16 + g, q1 = q0 + 8;
        int pix0 = (wi * WS + (q0 >> 4)) * WIMG + (wj * WS + (q0 & 15));
        int pix1 = (wi * WS + (q1 >> 4)) * WIMG + (wj * WS + (q1 & 15));
        float* o0 = g_ao + (size_t)pix0 * CDIM + head * HD;
        float* o1 = g_ao + (size_t)pix1 * CDIM + head * HD;
#pragma unroll
        for (int nj = 0; nj < 4; nj++) {
            int d = nj * 8 + 2 * tq;
            if (d < HD) {
                *(float2*)&o0[d] = make_float2(O[mi][nj][0] * inv0, O[mi][nj][1] * inv0);
                *(float2*)&o1[d] = make_float2(O[mi][nj][2] * inv1, O[mi][nj][3] * inv1);
            }
        }
    }
}

// ---------------- launch ----------------
extern "C" void kernel_launch(void* const* d_in, const int* in_sizes, int n_in,
                              void* d_out, int out_size) {
    const float* x    = (const float*)d_in[0];
    const int*   rpi  = (const int*)  d_in[1];
    const float* n1g  = (const float*)d_in[4];
    const float* n1b  = (const float*)d_in[5];
    const float* q_w  = (const float*)d_in[6];
    const float* q_b  = (const float*)d_in[7];
    const float* kv_w = (const float*)d_in[8];
    const float* kv_b = (const float*)d_in[9];
    const float* rpb  = (const float*)d_in[10];
    const float* p_w  = (const float*)d_in[11];
    const float* p_b  = (const float*)d_in[12];
    const float* n2g  = (const float*)d_in[13];
    const float* n2b  = (const float*)d_in[14];
    const float* w1   = (const float*)d_in[15];
    const float* b1   = (const float*)d_in[16];
    const float* w2   = (const float*)d_in[17];
    const float* b2   = (const float*)d_in[18];
    float* out = (float*)d_out;

    float  *p_qkv, *p_qkvw, *p_qkvb, *p_ao, *p_xo, *p_mh;
    float2 *p_ln1, *p_ln2;
    cudaGetSymbolAddress((void**)&p_qkv,  g_qkv);
    cudaGetSymbolAddress((void**)&p_qkvw, g_qkvw);
    cudaGetSymbolAddress((void**)&p_qkvb, g_qkvb);
    cudaGetSymbolAddress((void**)&p_ao,   g_ao);
    cudaGetSymbolAddress((void**)&p_xo,   g_xo);
    cudaGetSymbolAddress((void**)&p_mh,   g_mh);
    cudaGetSymbolAddress((void**)&p_ln1,  g_ln1);
    cudaGetSymbolAddress((void**)&p_ln2,  g_ln2);

    cudaFuncSetAttribute(mma_gemm<0,0>, cudaFuncAttributeMaxDynamicSharedMemorySize, GEMM_SMEM);
    cudaFuncSetAttribute(mma_gemm<0,1>, cudaFuncAttributeMaxDynamicSharedMemorySize, GEMM_SMEM);
    cudaFuncSetAttribute(mma_gemm<1,1>, cudaFuncAttributeMaxDynamicSharedMemorySize, GEMM_SMEM);

    dim3 lnBlk(32, 8);

    // 1. LN1 stats on x
    ln_stats_kernel<<<NPIX / 8, lnBlk>>>(x, p_ln1);
    // 2. bias table ([head][q][k]); 3. pack qkv weights
    bias_kernel<<<NQ, NKEY>>>(rpi, rpb);
    pack_qkv_kernel<<<(CDIM * QKVN + 255) / 256, 256>>>(q_w, kv_w, q_b, kv_b);
    // 4. qkv = LN1(x) @ [q_w|kv_w] + [q_b|kv_b]   (N=540)
    mma_gemm<0,1><<<dim3(9, NPIX / 128), 256, GEMM_SMEM>>>(
        x, p_qkvw, p_qkvb, nullptr, p_qkv, p_ln1, n1g, n1b, NPIX, QKVN, CDIM);
    // 5. windowed attention (bf16 tensor cores) -> g_ao
    attn_mma_kernel<<<dim3(NWIN * NWIN, NHEADS), 256>>>();
    // 6. xo = ao @ proj_w + proj_b + x
    mma_gemm<0,0><<<dim3(3, NPIX / 128), 256, GEMM_SMEM>>>(
        p_ao, p_w, p_b, x, p_xo, nullptr, nullptr, nullptr, NPIX, CDIM, CDIM);
    // 7. LN2 stats on xo
    ln_stats_kernel<<<NPIX / 8, lnBlk>>>(p_xo, p_ln2);
    // 8. mh = gelu(LN2(xo) @ w1 + b1)
    mma_gemm<1,1><<<dim3(6, NPIX / 128), 256, GEMM_SMEM>>>(
        p_xo, w1, b1, nullptr, p_mh, p_ln2, n2g, n2b, NPIX, MLPH, CDIM);
    // 9. out = mh @ w2 + b2 + xo
    mma_gemm<0,0><<<dim3(3, NPIX / 128), 256, GEMM_SMEM>>>(
        p_mh, w2, b2, p_xo, out, nullptr, nullptr, nullptr, NPIX, CDIM, MLPH);
}

// round 9
// speedup vs baseline: 1.1737x; 1.1737x over previous
#include <cuda_runtime.h>
#include <cuda_bf16.h>
#include <math.h>

// ---------------- problem constants ----------------
#define HIMG 256
#define WIMG 256
#define NPIX 65536            // HIMG*WIMG
#define CDIM 180
#define NHEADS 6
#define HD 30                 // CDIM / NHEADS
#define WS 16
#define OWS 24
#define PADW 4                // (OWS-WS)/2
#define NWIN 16               // windows per side
#define NQ 256                // WS*WS
#define NKEY 576              // OWS*OWS
#define MLPH 360
#define QKVN 540              // 180 (q) + 360 (kv)

// ---------------- scratch (device globals; no allocation allowed) ----------------
__device__ float  g_xn  [NPIX*CDIM];        // LN1(x), later reused for LN2(xo)
__device__ float  g_qkv [NPIX*QKVN];        // [pix][q(180) | k(180) | v(180)]
__device__ float  g_qkvw[CDIM*QKVN];        // packed [k][540] weights
__device__ float  g_qkvb[QKVN];             // packed bias
__device__ __nv_bfloat16 g_biasQh[NHEADS*NQ*NKEY];  // [head][query][key], bf16
__device__ float  g_ao [NPIX*CDIM];
__device__ float  g_xo [NPIX*CDIM];
__device__ float  g_mh [NPIX*MLPH];

// ---------------- LayerNorm: one warp per row of 180 ----------------
__global__ void ln_kernel(const float* __restrict__ x, const float* __restrict__ g,
                          const float* __restrict__ b, float* __restrict__ y) {
    int row  = blockIdx.x * blockDim.y + threadIdx.y;
    int lane = threadIdx.x;
    const float* xr = x + (size_t)row * CDIM;
    float v[6];
    float s = 0.f;
#pragma unroll
    for (int i = 0; i < 6; i++) {
        int d = lane + 32 * i;
        v[i] = (d < CDIM) ? xr[d] : 0.f;
        s += v[i];
    }
#pragma unroll
    for (int o = 16; o > 0; o >>= 1) s += __shfl_xor_sync(0xffffffffu, s, o);
    float mu = s * (1.f / CDIM);
    float vs = 0.f;
#pragma unroll
    for (int i = 0; i < 6; i++) {
        int d = lane + 32 * i;
        float dv = (d < CDIM) ? (v[i] - mu) : 0.f;
        vs += dv * dv;
    }
#pragma unroll
    for (int o = 16; o > 0; o >>= 1) vs += __shfl_xor_sync(0xffffffffu, vs, o);
    float inv = rsqrtf(vs * (1.f / CDIM) + 1e-5f);
    float* yr = y + (size_t)row * CDIM;
#pragma unroll
    for (int i = 0; i < 6; i++) {
        int d = lane + 32 * i;
        if (d < CDIM) yr[d] = g[d] * (v[i] - mu) * inv + b[d];
    }
}

// ---------------- pack [q_w | kv_w] -> g_qkvw, [q_b | kv_b] -> g_qkvb ----------------
__global__ void pack_qkv_kernel(const float* __restrict__ q_w, const float* __restrict__ kv_w,
                                const float* __restrict__ q_b, const float* __restrict__ kv_b) {
    int idx = blockIdx.x * blockDim.x + threadIdx.x;
    if (idx < CDIM * QKVN) {
        int k = idx / QKVN, n = idx - k * QKVN;
        g_qkvw[idx] = (n < CDIM) ? q_w[k * CDIM + n] : kv_w[k * 2 * CDIM + (n - CDIM)];
    }
    if (idx < QKVN)
        g_qkvb[idx] = (idx < CDIM) ? q_b[idx] : kv_b[idx - CDIM];
}

// ---------------- bias precompute (bf16): biasQh[h][q][k] = table[rpi[q,k], h] ----------------
__global__ void bias_kernel(const int* __restrict__ rpi, const float* __restrict__ table) {
    int q = blockIdx.x;       // 0..255
    int k = threadIdx.x;      // 0..575
    int t = rpi[q * NKEY + k];
#pragma unroll
    for (int h = 0; h < NHEADS; h++)
        g_biasQh[((size_t)h * NQ + q) * NKEY + k] = __float2bfloat16(table[t * NHEADS + h]);
}

// ---------------- tf32 tensor-core GEMM, double-buffered, paired smem (R7 inner loop) ----------------
__device__ __forceinline__ unsigned f2tf32(float v) {
    unsigned u;
    asm("cvt.rna.tf32.f32 %0, %1;" : "=r"(u) : "f"(v));
    return u;
}

#define AS_T  132
#define AS_KS 532
#define ABUF  2128      // 4*AS_KS (uint2)
#define BS_T  68
#define BS_KS 273
#define BBUF  1092      // 4*BS_KS (uint2)
#define STGSZ (ABUF + BBUF)               // 3220 uint2 per stage
#define GEMM_SMEM (2 * STGSZ * 8)         // 51520 bytes

template<int ACT>
__global__ void __launch_bounds__(256, 2) mma_gemm(
    const float* __restrict__ A, const float* __restrict__ B,
    const float* __restrict__ bias, const float* __restrict__ res,
    float* __restrict__ C, int M, int N, int K)
{
    extern __shared__ uint2 smbuf[];

    int bm = blockIdx.y * 128;
    int bn = blockIdx.x * 64;
    int t    = threadIdx.x;
    int lane = t & 31;
    int warp = t >> 5;
    int g  = lane >> 2;
    int tq = lane & 3;
    int wm = (warp >> 1) * 32;
    int wn = (warp & 1) * 32;

    float acc[2][4][4];
#pragma unroll
    for (int mi = 0; mi < 2; mi++)
#pragma unroll
        for (int ni = 0; ni < 4; ni++)
#pragma unroll
            for (int r = 0; r < 4; r++) acc[mi][ni][r] = 0.f;

    int kIters = (K + 31) >> 5;
    float4 ra[4], rb[2];

    auto gload = [&](int it) {
        int k0 = it * 32;
#pragma unroll
        for (int i = 0; i < 4; i++) {
            int idx = t + 256 * i;
            int m = idx >> 3, j = idx & 7;
            int gk = k0 + 4 * j;
            ra[i] = (gk < K) ? *(const float4*)&A[(size_t)(bm + m) * K + gk]
                             : make_float4(0.f, 0.f, 0.f, 0.f);
        }
#pragma unroll
        for (int i = 0; i < 2; i++) {
            int idx = t + 256 * i;
            int k = idx & 31, n = 4 * (idx >> 5);
            int gk = k0 + k, gn = bn + n;
            rb[i] = (gk < K && gn < N) ? *(const float4*)&B[(size_t)gk * N + gn]
                                       : make_float4(0.f, 0.f, 0.f, 0.f);
        }
    };

    auto sstore = [&](int s) {
        unsigned* ab = (unsigned*)(smbuf + s * STGSZ);
        unsigned* bb = (unsigned*)(smbuf + s * STGSZ + ABUF);
#pragma unroll
        for (int i = 0; i < 4; i++) {
            int idx = t + 256 * i;
            int m = idx >> 3, j = idx & 7;
            int ks = j >> 1, sel = j & 1;
            unsigned base = 2 * (ks * AS_KS + m) + sel;
            ab[base + 2 * (0 * AS_T)] = f2tf32(ra[i].x);
            ab[base + 2 * (1 * AS_T)] = f2tf32(ra[i].y);
            ab[base + 2 * (2 * AS_T)] = f2tf32(ra[i].z);
            ab[base + 2 * (3 * AS_T)] = f2tf32(ra[i].w);
        }
#pragma unroll
        for (int i = 0; i < 2; i++) {
            int idx = t + 256 * i;
            int k = idx & 31, n = 4 * (idx >> 5);
            int ks = k >> 3, tqq = k & 3, sel = (k >> 2) & 1;
            unsigned base = 2 * (ks * BS_KS + tqq * BS_T + n) + sel;
            bb[base + 0] = f2tf32(rb[i].x);
            bb[base + 2] = f2tf32(rb[i].y);
            bb[base + 4] = f2tf32(rb[i].z);
            bb[base + 6] = f2tf32(rb[i].w);
        }
    };

    auto compute = [&](int s) {
        const uint2* as = smbuf + s * STGSZ;
        const uint2* bs = as + ABUF;
#pragma unroll
        for (int ks = 0; ks < 4; ks++) {
            uint2 aLo[2], aHi[2], bp[4];
#pragma unroll
            for (int mi = 0; mi < 2; mi++) {
                int m0 = wm + mi * 16 + g;
                aLo[mi] = as[ks * AS_KS + tq * AS_T + m0];
                aHi[mi] = as[ks * AS_KS + tq * AS_T + m0 + 8];
            }
#pragma unroll
            for (int ni = 0; ni < 4; ni++)
                bp[ni] = bs[ks * BS_KS + tq * BS_T + wn + ni * 8 + g];
#pragma unroll
            for (int mi = 0; mi < 2; mi++)
#pragma unroll
                for (int ni = 0; ni < 4; ni++) {
                    asm volatile(
                        "mma.sync.aligned.m16n8k8.row.col.f32.tf32.tf32.f32 "
                        "{%0,%1,%2,%3}, {%4,%5,%6,%7}, {%8,%9}, {%0,%1,%2,%3};"
                        : "+f"(acc[mi][ni][0]), "+f"(acc[mi][ni][1]),
                          "+f"(acc[mi][ni][2]), "+f"(acc[mi][ni][3])
                        : "r"(aLo[mi].x), "r"(aHi[mi].x),
                          "r"(aLo[mi].y), "r"(aHi[mi].y),
                          "r"(bp[ni].x), "r"(bp[ni].y));
                }
        }
    };

    gload(0);
    sstore(0);
    __syncthreads();
    for (int it = 0; it < kIters; it++) {
        if (it + 1 < kIters) gload(it + 1);
        compute(it & 1);
        if (it + 1 < kIters) {
            sstore((it + 1) & 1);
            __syncthreads();
        }
    }

#pragma unroll
    for (int mi = 0; mi < 2; mi++) {
#pragma unroll
        for (int ni = 0; ni < 4; ni++) {
            int n = bn + wn + ni * 8 + 2 * tq;
            if (n >= N) continue;
            float bn0 = bias[n], bn1 = bias[n + 1];
#pragma unroll
            for (int half = 0; half < 2; half++) {
                int m = bm + wm + mi * 16 + g + half * 8;
                float v0 = acc[mi][ni][half * 2 + 0] + bn0;
                float v1 = acc[mi][ni][half * 2 + 1] + bn1;
                if (res) {
                    v0 += res[(size_t)m * N + n];
                    v1 += res[(size_t)m * N + n + 1];
                }
                if (ACT == 1) {
                    v0 = v0 * normcdff(v0);
                    v1 = v1 * normcdff(v1);
                }
                C[(size_t)m * N + n]     = v0;
                C[(size_t)m * N + n + 1] = v1;
            }
        }
    }
}

// ---------------- bf16 tensor-core windowed attention ----------------
// grid (256 windows, 6 heads), 256 threads = 8 warps, each warp owns 32 query
// rows. 9 chunks of 64 keys, no-max softmax (scores |s| << 1). OOB keys staged
// as zeros -> contribute exp(bias) to the denominator with v=0 (reference pad).
// Bias table is bf16 ([head][q][k]) to halve its L2 traffic.
__device__ __forceinline__ void mma_bf16(float* c, unsigned a0, unsigned a1,
                                         unsigned a2, unsigned a3,
                                         unsigned b0, unsigned b1) {
    asm volatile(
        "mma.sync.aligned.m16n8k16.row.col.f32.bf16.bf16.f32 "
        "{%0,%1,%2,%3}, {%4,%5,%6,%7}, {%8,%9}, {%0,%1,%2,%3};"
        : "+f"(c[0]), "+f"(c[1]), "+f"(c[2]), "+f"(c[3])
        : "r"(a0), "r"(a1), "r"(a2), "r"(a3), "r"(b0), "r"(b1));
}

__global__ void __launch_bounds__(256, 2) attn_mma_kernel() {
    int win  = blockIdx.x;
    int head = blockIdx.y;
    int wi = win >> 4, wj = win & 15;
    int t    = threadIdx.x;
    int lane = t & 31;
    int warp = t >> 5;
    int g  = lane >> 2;
    int tq = lane & 3;
    int wq = warp * 32;

    __shared__ __nv_bfloat16 Qs[NQ][40];    // stride 40: bank 20g+tq, conflict-free
    __shared__ __nv_bfloat16 Ks[64][40];
    __shared__ __nv_bfloat16 VsT[32][72];   // stride 72: rows 30/31 zeroed

    const float scale = 0.18257418583505537f;  // 30^-0.5

    // ---- stage Q (once) ----
    {
        int qi = t >> 4, qj = t & 15;
        int pix = (wi * WS + qi) * WIMG + (wj * WS + qj);
        const float* src = g_qkv + (size_t)pix * QKVN + head * HD;
#pragma unroll
        for (int j = 0; j < 15; j++) {
            float2 v = *(const float2*)&src[2 * j];
            *(__nv_bfloat162*)&Qs[t][2 * j] =
                __floats2bfloat162_rn(v.x * scale, v.y * scale);
        }
        *(__nv_bfloat162*)&Qs[t][30] = __floats2bfloat162_rn(0.f, 0.f);
    }
    __syncthreads();

    unsigned aq[2][2][4];
#pragma unroll
    for (int mi = 0; mi < 2; mi++) {
        int q0 = wq + mi * 16 + g, q1 = q0 + 8;
#pragma unroll
        for (int ks = 0; ks < 2; ks++) {
            int c0 = ks * 16 + 2 * tq;
            aq[mi][ks][0] = *(const unsigned*)&Qs[q0][c0];
            aq[mi][ks][1] = *(const unsigned*)&Qs[q1][c0];
            aq[mi][ks][2] = *(const unsigned*)&Qs[q0][c0 + 8];
            aq[mi][ks][3] = *(const unsigned*)&Qs[q1][c0 + 8];
        }
    }

    float O[2][4][4];
#pragma unroll
    for (int mi = 0; mi < 2; mi++)
#pragma unroll
        for (int nj = 0; nj < 4; nj++)
#pragma unroll
            for (int r = 0; r < 4; r++) O[mi][nj][r] = 0.f;
    float l0[2] = {0.f, 0.f}, l1[2] = {0.f, 0.f};

    int half  = t >> 7;         // 0: stage K, 1: stage V
    int key_l = (t & 127) >> 1; // key within chunk
    int part  = t & 1;          // which 15-dim half

    for (int ch = 0; ch < 9; ch++) {
        int cb = ch * 64;
        __syncthreads();
        {
            int key = cb + key_l;
            int ki = key / OWS;
            int kj = key - ki * OWS;
            int gr = wi * WS - PADW + ki;
            int gc = wj * WS - PADW + kj;
            bool ok = ((unsigned)gr < HIMG) && ((unsigned)gc < WIMG);
            const float* src = g_qkv + ((size_t)(gr * WIMG + gc)) * QKVN
                               + CDIM + half * CDIM + head * HD + part * 15;
            if (half == 0) {
#pragma unroll
                for (int d = 0; d < 15; d++)
                    Ks[key_l][part * 15 + d] = __float2bfloat16(ok ? src[d] : 0.f);
                if (part == 0)
                    *(__nv_bfloat162*)&Ks[key_l][30] = __floats2bfloat162_rn(0.f, 0.f);
            } else {
#pragma unroll
                for (int d = 0; d < 15; d++)
                    VsT[part * 15 + d][key_l] = __float2bfloat16(ok ? src[d] : 0.f);
                if (part == 0) {
                    VsT[30][key_l] = __float2bfloat16(0.f);
                    VsT[31][key_l] = __float2bfloat16(0.f);
                }
            }
        }
        __syncthreads();

        unsigned P[2][8][2];
#pragma unroll
        for (int mi = 0; mi < 2; mi++) {
            int q0 = wq + mi * 16 + g, q1 = q0 + 8;
            // bf16 bias rows; element index (…)*NKEY + cb + 2tq is even -> 4B aligned
            const __nv_bfloat162* bp0 = (const __nv_bfloat162*)
                (g_biasQh + ((size_t)head * NQ + q0) * NKEY + cb + 2 * tq);
            const __nv_bfloat162* bp1 = (const __nv_bfloat162*)
                (g_biasQh + ((size_t)head * NQ + q1) * NKEY + cb + 2 * tq);
#pragma unroll
            for (int ni = 0; ni < 8; ni++) {
                float c[4] = {0.f, 0.f, 0.f, 0.f};
                int krow = ni * 8 + g;
#pragma unroll
                for (int ks = 0; ks < 2; ks++) {
                    unsigned b0 = *(const unsigned*)&Ks[krow][ks * 16 + 2 * tq];
                    unsigned b1 = *(const unsigned*)&Ks[krow][ks * 16 + 2 * tq + 8];
                    mma_bf16(c, aq[mi][ks][0], aq[mi][ks][1], aq[mi][ks][2], aq[mi][ks][3], b0, b1);
                }
                float2 bA = __bfloat1622float2(bp0[ni * 4]);   // ni*8 bf16 = ni*4 bf16x2
                float2 bB = __bfloat1622float2(bp1[ni * 4]);
                float p0 = __expf(c[0] + bA.x);
                float p1 = __expf(c[1] + bA.y);
                float p2 = __expf(c[2] + bB.x);
                float p3 = __expf(c[3] + bB.y);
                l0[mi] += p0 + p1;
                l1[mi] += p2 + p3;
                __nv_bfloat162 h0 = __floats2bfloat162_rn(p0, p1);
                __nv_bfloat162 h1 = __floats2bfloat162_rn(p2, p3);
                P[mi][ni][0] = *(unsigned*)&h0;
                P[mi][ni][1] = *(unsigned*)&h1;
            }
        }

#pragma unroll
        for (int mi = 0; mi < 2; mi++)
#pragma unroll
            for (int nj = 0; nj < 4; nj++) {
                int drow = nj * 8 + g;
#pragma unroll
                for (int ks = 0; ks < 4; ks++) {
                    unsigned b0 = *(const unsigned*)&VsT[drow][ks * 16 + 2 * tq];
                    unsigned b1 = *(const unsigned*)&VsT[drow][ks * 16 + 2 * tq + 8];
                    mma_bf16(O[mi][nj],
                             P[mi][2 * ks][0], P[mi][2 * ks][1],
                             P[mi][2 * ks + 1][0], P[mi][2 * ks + 1][1],
                             b0, b1);
                }
            }
    }

#pragma unroll
    for (int mi = 0; mi < 2; mi++) {
        l0[mi] += __shfl_xor_sync(0xffffffffu, l0[mi], 1);
        l0[mi] += __shfl_xor_sync(0xffffffffu, l0[mi], 2);
        l1[mi] += __shfl_xor_sync(0xffffffffu, l1[mi], 1);
        l1[mi] += __shfl_xor_sync(0xffffffffu, l1[mi], 2);
    }
#pragma unroll
    for (int mi = 0; mi < 2; mi++) {
        float inv0 = 1.f / l0[mi];
        float inv1 = 1.f / l1[mi];
        int q0 = wq + mi * 16 + g, q1 = q0 + 8;
        int pix0 = (wi * WS + (q0 >> 4)) * WIMG + (wj * WS + (q0 & 15));
        int pix1 = (wi * WS + (q1 >> 4)) * WIMG + (wj * WS + (q1 & 15));
        float* o0 = g_ao + (size_t)pix0 * CDIM + head * HD;
        float* o1 = g_ao + (size_t)pix1 * CDIM + head * HD;
#pragma unroll
        for (int nj = 0; nj < 4; nj++) {
            int d = nj * 8 + 2 * tq;
            if (d < HD) {
                *(float2*)&o0[d] = make_float2(O[mi][nj][0] * inv0, O[mi][nj][1] * inv0);
                *(float2*)&o1[d] = make_float2(O[mi][nj][2] * inv1, O[mi][nj][3] * inv1);
            }
        }
    }
}

// ---------------- launch ----------------
extern "C" void kernel_launch(void* const* d_in, const int* in_sizes, int n_in,
                              void* d_out, int out_size) {
    const float* x    = (const float*)d_in[0];
    const int*   rpi  = (const int*)  d_in[1];
    const float* n1g  = (const float*)d_in[4];
    const float* n1b  = (const float*)d_in[5];
    const float* q_w  = (const float*)d_in[6];
    const float* q_b  = (const float*)d_in[7];
    const float* kv_w = (const float*)d_in[8];
    const float* kv_b = (const float*)d_in[9];
    const float* rpb  = (const float*)d_in[10];
    const float* p_w  = (const float*)d_in[11];
    const float* p_b  = (const float*)d_in[12];
    const float* n2g  = (const float*)d_in[13];
    const float* n2b  = (const float*)d_in[14];
    const float* w1   = (const float*)d_in[15];
    const float* b1   = (const float*)d_in[16];
    const float* w2   = (const float*)d_in[17];
    const float* b2   = (const float*)d_in[18];
    float* out = (float*)d_out;

    float *p_xn, *p_qkv, *p_qkvw, *p_qkvb, *p_ao, *p_xo, *p_mh;
    cudaGetSymbolAddress((void**)&p_xn,   g_xn);
    cudaGetSymbolAddress((void**)&p_qkv,  g_qkv);
    cudaGetSymbolAddress((void**)&p_qkvw, g_qkvw);
    cudaGetSymbolAddress((void**)&p_qkvb, g_qkvb);
    cudaGetSymbolAddress((void**)&p_ao,   g_ao);
    cudaGetSymbolAddress((void**)&p_xo,   g_xo);
    cudaGetSymbolAddress((void**)&p_mh,   g_mh);

    cudaFuncSetAttribute(mma_gemm<0>, cudaFuncAttributeMaxDynamicSharedMemorySize, GEMM_SMEM);
    cudaFuncSetAttribute(mma_gemm<1>, cudaFuncAttributeMaxDynamicSharedMemorySize, GEMM_SMEM);

    dim3 lnBlk(32, 8);

    // 1. xn = LN1(x)
    ln_kernel<<<NPIX / 8, lnBlk>>>(x, n1g, n1b, p_xn);
    // 2. bias table (bf16, [head][q][k]); 3. pack qkv weights
    bias_kernel<<<NQ, NKEY>>>(rpi, rpb);
    pack_qkv_kernel<<<(CDIM * QKVN + 255) / 256, 256>>>(q_w, kv_w, q_b, kv_b);
    // 4. qkv = xn @ [q_w|kv_w] + [q_b|kv_b]   (N=540)
    mma_gemm<0><<<dim3(9, NPIX / 128), 256, GEMM_SMEM>>>(
        p_xn, p_qkvw, p_qkvb, nullptr, p_qkv, NPIX, QKVN, CDIM);
    // 5. windowed attention (bf16 tensor cores) -> g_ao
    attn_mma_kernel<<<dim3(NWIN * NWIN, NHEADS), 256>>>();
    // 6. xo = ao @ proj_w + proj_b + x
    mma_gemm<0><<<dim3(3, NPIX / 128), 256, GEMM_SMEM>>>(
        p_ao, p_w, p_b, x, p_xo, NPIX, CDIM, CDIM);
    // 7. xn = LN2(xo)   (reuse g_xn)
    ln_kernel<<<NPIX / 8, lnBlk>>>(p_xo, n2g, n2b, p_xn);
    // 8. mh = gelu(xn @ w1 + b1)
    mma_gemm<1><<<dim3(6, NPIX / 128), 256, GEMM_SMEM>>>(
        p_xn, w1, b1, nullptr, p_mh, NPIX, MLPH, CDIM);
    // 9. out = mh @ w2 + b2 + xo
    mma_gemm<0><<<dim3(3, NPIX / 128), 256, GEMM_SMEM>>>(
        p_mh, w2, b2, p_xo, out, NPIX, CDIM, MLPH);
}

// round 16
// speedup vs baseline: 1.3808x; 1.1765x over previous
#include <cuda_runtime.h>
#include <cuda_bf16.h>
#include <math.h>

// ---------------- problem constants ----------------
#define HIMG 256
#define WIMG 256
#define NPIX 65536            // HIMG*WIMG
#define CDIM 180
#define NHEADS 6
#define HD 30                 // CDIM / NHEADS
#define WS 16
#define OWS 24
#define PADW 4                // (OWS-WS)/2
#define NWIN 16               // windows per side
#define NQ 256                // WS*WS
#define NKEY 576              // OWS*OWS
#define MLPH 360
#define QKVN 540              // 180 (q) + 360 (kv)

// padded bf16 row strides (16B-aligned rows)
#define XSTR 192              // for xn / ao (180 + 12 zero pad)
#define QSTR 544              // for qkv (540 + 4 pad)
#define MSTR 384              // for mh (360 + 24 zero pad)

#define QK_SCALE 0.18257418583505537f   // 30^-0.5

// ---------------- scratch (device globals; no allocation allowed) ----------------
__device__ __nv_bfloat16 g_xn [NPIX*XSTR];   // LN1(x) then LN2(xo)
__device__ __nv_bfloat16 g_qkv[NPIX*QSTR];   // [pix][q*scale(180)|k(180)|v(180)]
__device__ float  g_qkvw[CDIM*QKVN];         // packed fp32 weights (q part pre-scaled)
__device__ float  g_qkvb[QKVN];
__device__ __nv_bfloat16 g_biasQh[NHEADS*NQ*NKEY];  // [head][query][key]
__device__ __nv_bfloat16 g_ao [NPIX*XSTR];
__device__ float  g_xo [NPIX*CDIM];
__device__ __nv_bfloat16 g_mh [NPIX*MSTR];

// ---------------- LayerNorm: one warp per row of 180; bf16 out (pad zeroed) ----------------
__global__ void ln_kernel(const float* __restrict__ x, const float* __restrict__ g,
                          const float* __restrict__ b, __nv_bfloat16* __restrict__ y) {
    int row  = blockIdx.x * blockDim.y + threadIdx.y;
    int lane = threadIdx.x;
    const float* xr = x + (size_t)row * CDIM;
    float v[6];
    float s = 0.f;
#pragma unroll
    for (int i = 0; i < 6; i++) {
        int d = lane + 32 * i;
        v[i] = (d < CDIM) ? xr[d] : 0.f;
        s += v[i];
    }
#pragma unroll
    for (int o = 16; o > 0; o >>= 1) s += __shfl_xor_sync(0xffffffffu, s, o);
    float mu = s * (1.f / CDIM);
    float vs = 0.f;
#pragma unroll
    for (int i = 0; i < 6; i++) {
        int d = lane + 32 * i;
        float dv = (d < CDIM) ? (v[i] - mu) : 0.f;
        vs += dv * dv;
    }
#pragma unroll
    for (int o = 16; o > 0; o >>= 1) vs += __shfl_xor_sync(0xffffffffu, vs, o);
    float inv = rsqrtf(vs * (1.f / CDIM) + 1e-5f);
    __nv_bfloat16* yr = y + (size_t)row * XSTR;
#pragma unroll
    for (int i = 0; i < 6; i++) {
        int d = lane + 32 * i;
        if (d < CDIM)      yr[d] = __float2bfloat16(g[d] * (v[i] - mu) * inv + b[d]);
        else if (d < XSTR) yr[d] = __float2bfloat16(0.f);   // zero pad 180..191
    }
}

// ---------------- pack [q_w*scale | kv_w] -> g_qkvw (fp32), bias likewise ----------------
__global__ void pack_qkv_kernel(const float* __restrict__ q_w, const float* __restrict__ kv_w,
                                const float* __restrict__ q_b, const float* __restrict__ kv_b) {
    int idx = blockIdx.x * blockDim.x + threadIdx.x;
    if (idx < CDIM * QKVN) {
        int k = idx / QKVN, n = idx - k * QKVN;
        g_qkvw[idx] = (n < CDIM) ? q_w[k * CDIM + n] * QK_SCALE
                                 : kv_w[k * 2 * CDIM + (n - CDIM)];
    }
    if (idx < QKVN)
        g_qkvb[idx] = (idx < CDIM) ? q_b[idx] * QK_SCALE : kv_b[idx - CDIM];
}

// ---------------- bias precompute (bf16): biasQh[h][q][k] = table[rpi[q,k], h] ----------------
__global__ void bias_kernel(const int* __restrict__ rpi, const float* __restrict__ table) {
    int q = blockIdx.x;       // 0..255
    int k = threadIdx.x;      // 0..575
    int t = rpi[q * NKEY + k];
#pragma unroll
    for (int h = 0; h < NHEADS; h++)
        g_biasQh[((size_t)h * NQ + q) * NKEY + k] = __float2bfloat16(table[t * NHEADS + h]);
}

// ---------------- helpers ----------------
__device__ __forceinline__ void mma_bf16(float* c, unsigned a0, unsigned a1,
                                         unsigned a2, unsigned a3,
                                         unsigned b0, unsigned b1) {
    asm volatile(
        "mma.sync.aligned.m16n8k16.row.col.f32.bf16.bf16.f32 "
        "{%0,%1,%2,%3}, {%4,%5,%6,%7}, {%8,%9}, {%0,%1,%2,%3};"
        : "+f"(c[0]), "+f"(c[1]), "+f"(c[2]), "+f"(c[3])
        : "r"(a0), "r"(a1), "r"(a2), "r"(a3), "r"(b0), "r"(b1));
}

__device__ __forceinline__ unsigned pack_bf2(float a, float b) {
    __nv_bfloat162 h = __floats2bfloat162_rn(a, b);
    return *(unsigned*)&h;
}

// ---------------- bf16 GEMM core (device template; wrapped by concrete kernels) ----------------
// C = act(A@B + bias [+ res]). A: bf16 [M][kstr] (pad cols zero), B: fp32 [kdim][nreal].
// BM=128, BN=64, BK=32. 8 warps (4m x 2n), warp tile 32x32 = 2x4 m16n8k16 mmas.
// Smem uint2 = {bf16x2(k=c,c+1), bf16x2(k=c+8,c+9)}: one LDS.64 per fragment.
// Epilogue: n<nreal -> value; nreal<=n<nzero -> zero (bf16 out only); else skip.
// NOTE: parameter names deliberately lowercase — NZERO is a POSIX macro in <limits.h>.
#define G_AT   132
#define G_AKS  536
#define G_ABUF 1072     // 2*G_AKS (uint2)
#define G_BT   68
#define G_BKS  272
#define G_BBUF 544      // 2*G_BKS (uint2)
#define G_STG  (G_ABUF + G_BBUF)          // 1616 uint2
#define GEMM_SMEM (2 * G_STG * 8)         // 25856 bytes

template<int ACT, typename CT>
__device__ __forceinline__ void gemm_body(
    uint2* smbuf,
    const __nv_bfloat16* amat, int kstr,
    const float* bmat,
    const float* bvec, const float* rmat, int rstr,
    CT* cmat, int nstr, int nzero,
    int nreal, int kdim)
{
    int bm = blockIdx.y * 128;
    int bn = blockIdx.x * 64;
    int t    = threadIdx.x;
    int lane = t & 31;
    int warp = t >> 5;
    int g  = lane >> 2;
    int tq = lane & 3;
    int wm = (warp >> 1) * 32;
    int wn = (warp & 1) * 32;

    float acc[2][4][4];
#pragma unroll
    for (int mi = 0; mi < 2; mi++)
#pragma unroll
        for (int ni = 0; ni < 4; ni++)
#pragma unroll
            for (int r = 0; r < 4; r++) acc[mi][ni][r] = 0.f;

    int kIters = (kdim + 31) >> 5;

    uint4 ra0, ra1;                 // A: 16 bf16 of (mrow, 16ks + 0..15)
    float4 fb0, fb1, fb2, fb3;      // B rows k,k+1,k+8,k+9 x 4 cols (t<128 only)
    int amr = t >> 1, aks = t & 1;
    int bng = t & 15, btq = (t >> 4) & 3, bks = t >> 6;   // valid for t<128

    auto gload = [&](int it) {
        int k0 = it * 32;
        const uint4* asrc = (const uint4*)(amat + (size_t)(bm + amr) * kstr + k0 + 16 * aks);
        ra0 = asrc[0];
        ra1 = asrc[1];
        if (t < 128) {
            int k = k0 + 16 * bks + 2 * btq;
            int n0 = bn + 4 * bng;
            bool nok = n0 < nreal;
            float4 z = make_float4(0.f, 0.f, 0.f, 0.f);
            fb0 = (nok && k     < kdim) ? *(const float4*)&bmat[(size_t)(k    ) * nreal + n0] : z;
            fb1 = (nok && k + 1 < kdim) ? *(const float4*)&bmat[(size_t)(k + 1) * nreal + n0] : z;
            fb2 = (nok && k + 8 < kdim) ? *(const float4*)&bmat[(size_t)(k + 8) * nreal + n0] : z;
            fb3 = (nok && k + 9 < kdim) ? *(const float4*)&bmat[(size_t)(k + 9) * nreal + n0] : z;
        }
    };

    auto sstore = [&](int s) {
        uint2* ab = smbuf + s * G_STG;
        uint2* bb = ab + G_ABUF;
        unsigned base = aks * G_AKS + amr;
        ab[base + 0 * G_AT] = make_uint2(ra0.x, ra1.x);
        ab[base + 1 * G_AT] = make_uint2(ra0.y, ra1.y);
        ab[base + 2 * G_AT] = make_uint2(ra0.z, ra1.z);
        ab[base + 3 * G_AT] = make_uint2(ra0.w, ra1.w);
        if (t < 128) {
            uint2 w0 = make_uint2(pack_bf2(fb0.x, fb1.x), pack_bf2(fb2.x, fb3.x));
            uint2 w1 = make_uint2(pack_bf2(fb0.y, fb1.y), pack_bf2(fb2.y, fb3.y));
            uint2 w2 = make_uint2(pack_bf2(fb0.z, fb1.z), pack_bf2(fb2.z, fb3.z));
            uint2 w3 = make_uint2(pack_bf2(fb0.w, fb1.w), pack_bf2(fb2.w, fb3.w));
            uint4* dst = (uint4*)&bb[bks * G_BKS + btq * G_BT + 4 * bng];
            dst[0] = make_uint4(w0.x, w0.y, w1.x, w1.y);
            dst[1] = make_uint4(w2.x, w2.y, w3.x, w3.y);
        }
    };

    auto compute = [&](int s) {
        const uint2* as = smbuf + s * G_STG;
        const uint2* bs = as + G_ABUF;
#pragma unroll
        for (int ks = 0; ks < 2; ks++) {
            uint2 aLo[2], aHi[2], bp[4];
#pragma unroll
            for (int mi = 0; mi < 2; mi++) {
                int m0 = wm + mi * 16 + g;
                aLo[mi] = as[ks * G_AKS + tq * G_AT + m0];
                aHi[mi] = as[ks * G_AKS + tq * G_AT + m0 + 8];
            }
#pragma unroll
            for (int ni = 0; ni < 4; ni++)
                bp[ni] = bs[ks * G_BKS + tq * G_BT + wn + ni * 8 + g];
#pragma unroll
            for (int mi = 0; mi < 2; mi++)
#pragma unroll
                for (int ni = 0; ni < 4; ni++)
                    mma_bf16(acc[mi][ni],
                             aLo[mi].x, aHi[mi].x, aLo[mi].y, aHi[mi].y,
                             bp[ni].x, bp[ni].y);
        }
    };

    gload(0);
    sstore(0);
    __syncthreads();
    for (int it = 0; it < kIters; it++) {
        if (it + 1 < kIters) gload(it + 1);
        compute(it & 1);
        if (it + 1 < kIters) {
            sstore((it + 1) & 1);
            __syncthreads();
        }
    }

    // ---- epilogue ----
    const bool isBF = (sizeof(CT) == 2);
#pragma unroll
    for (int mi = 0; mi < 2; mi++) {
#pragma unroll
        for (int ni = 0; ni < 4; ni++) {
            int n = bn + wn + ni * 8 + 2 * tq;
            if (n < nreal) {
                float bn0 = bvec[n], bn1 = bvec[n + 1];
#pragma unroll
                for (int half = 0; half < 2; half++) {
                    int m = bm + wm + mi * 16 + g + half * 8;
                    float v0 = acc[mi][ni][half * 2 + 0] + bn0;
                    float v1 = acc[mi][ni][half * 2 + 1] + bn1;
                    if (rmat) {
                        v0 += rmat[(size_t)m * rstr + n];
                        v1 += rmat[(size_t)m * rstr + n + 1];
                    }
                    if (ACT == 1) {
                        v0 = v0 * normcdff(v0);
                        v1 = v1 * normcdff(v1);
                    }
                    if (isBF) {
                        *(__nv_bfloat162*)((__nv_bfloat16*)cmat + (size_t)m * nstr + n) =
                            __floats2bfloat162_rn(v0, v1);
                    } else {
                        float* cf = (float*)cmat;
                        cf[(size_t)m * nstr + n]     = v0;
                        cf[(size_t)m * nstr + n + 1] = v1;
                    }
                }
            } else if (isBF && n < nzero) {
#pragma unroll
                for (int half = 0; half < 2; half++) {
                    int m = bm + wm + mi * 16 + g + half * 8;
                    *(__nv_bfloat162*)((__nv_bfloat16*)cmat + (size_t)m * nstr + n) =
                        __floats2bfloat162_rn(0.f, 0.f);
                }
            }
        }
    }
}

// ---- concrete (non-template) GEMM kernels ----
__global__ void __launch_bounds__(256, 2) gemm_qkv_kernel() {
    extern __shared__ uint2 smbuf[];
    gemm_body<0, __nv_bfloat16>(smbuf, g_xn, XSTR, g_qkvw, g_qkvb,
                                (const float*)nullptr, 0,
                                g_qkv, QSTR, QSTR, QKVN, CDIM);
}
__global__ void __launch_bounds__(256, 2) gemm_proj_kernel(
    const float* pw, const float* pb, const float* resx, float* xo) {
    extern __shared__ uint2 smbuf[];
    gemm_body<0, float>(smbuf, g_ao, XSTR, pw, pb, resx, CDIM,
                        xo, CDIM, CDIM, CDIM, CDIM);
}
__global__ void __launch_bounds__(256, 2) gemm_mlp1_kernel(
    const float* w1, const float* b1) {
    extern __shared__ uint2 smbuf[];
    gemm_body<1, __nv_bfloat16>(smbuf, g_xn, XSTR, w1, b1,
                                (const float*)nullptr, 0,
                                g_mh, MSTR, MSTR, MLPH, CDIM);
}
__global__ void __launch_bounds__(256, 2) gemm_mlp2_kernel(
    const float* w2, const float* b2, const float* xo, float* outp) {
    extern __shared__ uint2 smbuf[];
    gemm_body<0, float>(smbuf, g_mh, MSTR, w2, b2, xo, CDIM,
                        outp, CDIM, CDIM, CDIM, MLPH);
}

// ---------------- bf16 tensor-core windowed attention ----------------
// grid (256 windows, 6 heads), 256 threads = 8 warps x 32 query rows.
// 9 chunks of 64 keys, no-max softmax (|s| << 1). OOB keys staged as zeros ->
// contribute exp(bias) to denominator with v=0 (reference pad semantics).
// Reads bf16 qkv directly (scale pre-folded into q weights); writes bf16 ao.
__global__ void __launch_bounds__(256, 2) attn_mma_kernel() {
    int win  = blockIdx.x;
    int head = blockIdx.y;
    int wi = win >> 4, wj = win & 15;
    int t    = threadIdx.x;
    int lane = t & 31;
    int warp = t >> 5;
    int g  = lane >> 2;
    int tq = lane & 3;
    int wq = warp * 32;

    __shared__ __nv_bfloat16 Qs[NQ][40];    // stride 40: bank 20g+tq, conflict-free
    __shared__ __nv_bfloat16 Ks[64][40];
    __shared__ __nv_bfloat16 VsT[32][72];   // rows 30/31 zeroed

    // ---- stage Q (once): pure bf16 copy, scale already folded ----
    {
        int qi = t >> 4, qj = t & 15;
        int pix = (wi * WS + qi) * WIMG + (wj * WS + qj);
        const unsigned* src = (const unsigned*)(g_qkv + (size_t)pix * QSTR + head * HD);
#pragma unroll
        for (int j = 0; j < 15; j++)
            *(unsigned*)&Qs[t][2 * j] = src[j];
        *(unsigned*)&Qs[t][30] = 0u;
    }
    __syncthreads();

    unsigned aq[2][2][4];
#pragma unroll
    for (int mi = 0; mi < 2; mi++) {
        int q0 = wq + mi * 16 + g, q1 = q0 + 8;
#pragma unroll
        for (int ks = 0; ks < 2; ks++) {
            int c0 = ks * 16 + 2 * tq;
            aq[mi][ks][0] = *(const unsigned*)&Qs[q0][c0];
            aq[mi][ks][1] = *(const unsigned*)&Qs[q1][c0];
            aq[mi][ks][2] = *(const unsigned*)&Qs[q0][c0 + 8];
            aq[mi][ks][3] = *(const unsigned*)&Qs[q1][c0 + 8];
        }
    }

    float O[2][4][4];
#pragma unroll
    for (int mi = 0; mi < 2; mi++)
#pragma unroll
        for (int nj = 0; nj < 4; nj++)
#pragma unroll
            for (int r = 0; r < 4; r++) O[mi][nj][r] = 0.f;
    float l0[2] = {0.f, 0.f}, l1[2] = {0.f, 0.f};

    int half  = t >> 7;         // 0: stage K, 1: stage V
    int key_l = (t & 127) >> 1; // key within chunk
    int part  = t & 1;          // uint range: part0 j=0..6, part1 j=7..14

    for (int ch = 0; ch < 9; ch++) {
        int cb = ch * 64;
        __syncthreads();
        {
            int key = cb + key_l;
            int ki = key / OWS;
            int kj = key - ki * OWS;
            int gr = wi * WS - PADW + ki;
            int gc = wj * WS - PADW + kj;
            bool ok = ((unsigned)gr < HIMG) && ((unsigned)gc < WIMG);
            const unsigned* src = (const unsigned*)
                (g_qkv + ((size_t)(gr * WIMG + gc)) * QSTR + CDIM + half * CDIM + head * HD);
            if (half == 0) {
                if (part == 0) {
#pragma unroll
                    for (int j = 0; j < 7; j++)
                        *(unsigned*)&Ks[key_l][2 * j] = ok ? src[j] : 0u;
                } else {
#pragma unroll
                    for (int j = 7; j < 15; j++)
                        *(unsigned*)&Ks[key_l][2 * j] = ok ? src[j] : 0u;
                    *(unsigned*)&Ks[key_l][30] = 0u;
                }
            } else {
                if (part == 0) {
#pragma unroll
                    for (int j = 0; j < 7; j++) {
                        unsigned u = ok ? src[j] : 0u;
                        __nv_bfloat162 p = *(__nv_bfloat162*)&u;
                        VsT[2 * j][key_l]     = p.x;
                        VsT[2 * j + 1][key_l] = p.y;
                    }
                    VsT[30][key_l] = __float2bfloat16(0.f);
                    VsT[31][key_l] = __float2bfloat16(0.f);
                } else {
#pragma unroll
                    for (int j = 7; j < 15; j++) {
                        unsigned u = ok ? src[j] : 0u;
                        __nv_bfloat162 p = *(__nv_bfloat162*)&u;
                        VsT[2 * j][key_l]     = p.x;
                        VsT[2 * j + 1][key_l] = p.y;
                    }
                }
            }
        }
        __syncthreads();

        unsigned P[2][8][2];
#pragma unroll
        for (int mi = 0; mi < 2; mi++) {
            int q0 = wq + mi * 16 + g, q1 = q0 + 8;
            const __nv_bfloat162* bp0 = (const __nv_bfloat162*)
                (g_biasQh + ((size_t)head * NQ + q0) * NKEY + cb + 2 * tq);
            const __nv_bfloat162* bp1 = (const __nv_bfloat162*)
                (g_biasQh + ((size_t)head * NQ + q1) * NKEY + cb + 2 * tq);
#pragma unroll
            for (int ni = 0; ni < 8; ni++) {
                float c[4] = {0.f, 0.f, 0.f, 0.f};
                int krow = ni * 8 + g;
#pragma unroll
                for (int ks = 0; ks < 2; ks++) {
                    unsigned b0 = *(const unsigned*)&Ks[krow][ks * 16 + 2 * tq];
                    unsigned b1 = *(const unsigned*)&Ks[krow][ks * 16 + 2 * tq + 8];
                    mma_bf16(c, aq[mi][ks][0], aq[mi][ks][1], aq[mi][ks][2], aq[mi][ks][3], b0, b1);
                }
                float2 bA = __bfloat1622float2(bp0[ni * 4]);
                float2 bB = __bfloat1622float2(bp1[ni * 4]);
                float p0 = __expf(c[0] + bA.x);
                float p1 = __expf(c[1] + bA.y);
                float p2 = __expf(c[2] + bB.x);
                float p3 = __expf(c[3] + bB.y);
                l0[mi] += p0 + p1;
                l1[mi] += p2 + p3;
                P[mi][ni][0] = pack_bf2(p0, p1);
                P[mi][ni][1] = pack_bf2(p2, p3);
            }
        }

#pragma unroll
        for (int mi = 0; mi < 2; mi++)
#pragma unroll
            for (int nj = 0; nj < 4; nj++) {
                int drow = nj * 8 + g;
#pragma unroll
                for (int ks = 0; ks < 4; ks++) {
                    unsigned b0 = *(const unsigned*)&VsT[drow][ks * 16 + 2 * tq];
                    unsigned b1 = *(const unsigned*)&VsT[drow][ks * 16 + 2 * tq + 8];
                    mma_bf16(O[mi][nj],
                             P[mi][2 * ks][0], P[mi][2 * ks][1],
                             P[mi][2 * ks + 1][0], P[mi][2 * ks + 1][1],
                             b0, b1);
                }
            }
    }

#pragma unroll
    for (int mi = 0; mi < 2; mi++) {
        l0[mi] += __shfl_xor_sync(0xffffffffu, l0[mi], 1);
        l0[mi] += __shfl_xor_sync(0xffffffffu, l0[mi], 2);
        l1[mi] += __shfl_xor_sync(0xffffffffu, l1[mi], 1);
        l1[mi] += __shfl_xor_sync(0xffffffffu, l1[mi], 2);
    }
#pragma unroll
    for (int mi = 0; mi < 2; mi++) {
        float inv0 = 1.f / l0[mi];
        float inv1 = 1.f / l1[mi];
        int q0 = wq + mi * 16 + g, q1 = q0 + 8;
        int pix0 = (wi * WS + (q0 >> 4)) * WIMG + (wj * WS + (q0 & 15));
        int pix1 = (wi * WS + (q1 >> 4)) * WIMG + (wj * WS + (q1 & 15));
        __nv_bfloat16* o0 = g_ao + (size_t)pix0 * XSTR + head * HD;
        __nv_bfloat16* o1 = g_ao + (size_t)pix1 * XSTR + head * HD;
#pragma unroll
        for (int nj = 0; nj < 4; nj++) {
            int d = nj * 8 + 2 * tq;
            if (d < HD) {
                *(__nv_bfloat162*)&o0[d] =
                    __floats2bfloat162_rn(O[mi][nj][0] * inv0, O[mi][nj][1] * inv0);
                *(__nv_bfloat162*)&o1[d] =
                    __floats2bfloat162_rn(O[mi][nj][2] * inv1, O[mi][nj][3] * inv1);
            }
        }
        // head-0 blocks zero the pad cols 180..191 of each pixel row
        if (head == 0) {
            __nv_bfloat162 z2 = __floats2bfloat162_rn(0.f, 0.f);
            __nv_bfloat16* r0 = g_ao + (size_t)pix0 * XSTR;
            __nv_bfloat16* r1 = g_ao + (size_t)pix1 * XSTR;
            *(__nv_bfloat162*)&r0[180 + 2 * tq] = z2;
            *(__nv_bfloat162*)&r1[180 + 2 * tq] = z2;
            if (tq < 2) {
                *(__nv_bfloat162*)&r0[188 + 2 * tq] = z2;
                *(__nv_bfloat162*)&r1[188 + 2 * tq] = z2;
            }
        }
    }
}

// ---------------- launch ----------------
extern "C" void kernel_launch(void* const* d_in, const int* in_sizes, int n_in,
                              void* d_out, int out_size) {
    const float* x    = (const float*)d_in[0];
    const int*   rpi  = (const int*)  d_in[1];
    const float* n1g  = (const float*)d_in[4];
    const float* n1b  = (const float*)d_in[5];
    const float* q_w  = (const float*)d_in[6];
    const float* q_b  = (const float*)d_in[7];
    const float* kv_w = (const float*)d_in[8];
    const float* kv_b = (const float*)d_in[9];
    const float* rpb  = (const float*)d_in[10];
    const float* p_w  = (const float*)d_in[11];
    const float* p_b  = (const float*)d_in[12];
    const float* n2g  = (const float*)d_in[13];
    const float* n2b  = (const float*)d_in[14];
    const float* w1   = (const float*)d_in[15];
    const float* b1   = (const float*)d_in[16];
    const float* w2   = (const float*)d_in[17];
    const float* b2   = (const float*)d_in[18];
    float* out = (float*)d_out;

    __nv_bfloat16 *p_xn;
    float *p_xo;
    cudaGetSymbolAddress((void**)&p_xn, g_xn);
    cudaGetSymbolAddress((void**)&p_xo, g_xo);

    cudaFuncSetAttribute(gemm_qkv_kernel,  cudaFuncAttributeMaxDynamicSharedMemorySize, GEMM_SMEM);
    cudaFuncSetAttribute(gemm_proj_kernel, cudaFuncAttributeMaxDynamicSharedMemorySize, GEMM_SMEM);
    cudaFuncSetAttribute(gemm_mlp1_kernel, cudaFuncAttributeMaxDynamicSharedMemorySize, GEMM_SMEM);
    cudaFuncSetAttribute(gemm_mlp2_kernel, cudaFuncAttributeMaxDynamicSharedMemorySize, GEMM_SMEM);

    dim3 lnBlk(32, 8);

    // 1. xn = LN1(x) (bf16, stride 192, pad zeroed)
    ln_kernel<<<NPIX / 8, lnBlk>>>(x, n1g, n1b, p_xn);
    // 2. bias table (bf16); 3. pack qkv weights (q pre-scaled)
    bias_kernel<<<NQ, NKEY>>>(rpi, rpb);
    pack_qkv_kernel<<<(CDIM * QKVN + 255) / 256, 256>>>(q_w, kv_w, q_b, kv_b);
    // 4. qkv = xn @ [q_w*s|kv_w] + bias  (bf16 out, stride 544; 9*64=576 covers 544 zero pad)
    gemm_qkv_kernel<<<dim3(9, NPIX / 128), 256, GEMM_SMEM>>>();
    // 5. windowed attention -> ao (bf16, stride 192)
    attn_mma_kernel<<<dim3(NWIN * NWIN, NHEADS), 256>>>();
    // 6. xo = ao @ proj_w + proj_b + x   (fp32 out)
    gemm_proj_kernel<<<dim3(3, NPIX / 128), 256, GEMM_SMEM>>>(p_w, p_b, x, p_xo);
    // 7. xn = LN2(xo) (reuse g_xn)
    ln_kernel<<<NPIX / 8, lnBlk>>>(p_xo, n2g, n2b, p_xn);
    // 8. mh = gelu(xn @ w1 + b1)  (bf16 out, stride 384; 6*64=384 covers zero pad)
    gemm_mlp1_kernel<<<dim3(6, NPIX / 128), 256, GEMM_SMEM>>>(w1, b1);
    // 9. out = mh @ w2 + b2 + xo  (fp32 out)
    gemm_mlp2_kernel<<<dim3(3, NPIX / 128), 256, GEMM_SMEM>>>(w2, b2, p_xo, out);
}